// round 13
// baseline (speedup 1.0000x reference)
#include <cuda_runtime.h>
#include <cuda_fp16.h>
#include <cstdint>

// ---------------- problem constants ----------------
#define NB     65536
#define MPAD   65664     // 342 * 192 (gemm1 M-tile padding)
#define IN1    384
#define IN2    128
#define KDIM   512
#define G1U    384
#define N1     1152
#define G2U    16
#define NLEV   256

typedef unsigned long long u64;
typedef unsigned int u32;

// ---------------- device scratch ----------------
__device__ __half g_Ah[(size_t)MPAD * KDIM];   // fp16 concat(x1,x2), padded rows stay 0
__device__ __half g_Bh[(size_t)N1 * KDIM];     // reordered+transposed W1
__device__ __half g_h1h[(size_t)MPAD * G1U];   // fp16 h1 (padded)
__device__ __half g_B2[(size_t)48 * G1U];      // transposed W2
__device__ __half g_h2h[(size_t)NB * G2U];     // fp16 h2
__device__ u32    g_Wf1[2048];                 // head W1 in MMA B-fragment order
__device__ u32    g_Wf2[2048];                 // head W2 in MMA B-fragment order

// ---------------- helpers ----------------
__device__ __forceinline__ u32 smem_u32(const void* p) {
    u32 a;
    asm("{ .reg .u64 t; cvta.to.shared.u64 t, %1; cvt.u32.u64 %0, t; }" : "=r"(a) : "l"(p));
    return a;
}
__device__ __forceinline__ u32 swz(u32 x) { return x ^ ((x >> 3) & 0x70); }

#define CP_ASYNC16(dst, src) \
    asm volatile("cp.async.cg.shared.global [%0], [%1], 16;" :: "r"(dst), "l"(src) : "memory")
#define CP_COMMIT() asm volatile("cp.async.commit_group;" ::: "memory")
#define CP_WAIT1()  asm volatile("cp.async.wait_group 1;" ::: "memory")

#define LDSM_X4(r0, r1, r2, r3, addr) \
    asm volatile("ldmatrix.sync.aligned.m8n8.x4.shared.b16 {%0,%1,%2,%3}, [%4];" \
        : "=r"(r0), "=r"(r1), "=r"(r2), "=r"(r3) : "r"(addr))

#define MMA16816(d, a, b) \
    asm volatile("mma.sync.aligned.m16n8k16.row.col.f32.f16.f16.f32 " \
        "{%0,%1,%2,%3},{%4,%5,%6,%7},{%8,%9},{%0,%1,%2,%3};" \
        : "+f"((d)[0]), "+f"((d)[1]), "+f"((d)[2]), "+f"((d)[3]) \
        : "r"((a)[0]), "r"((a)[1]), "r"((a)[2]), "r"((a)[3]), "r"((b)[0]), "r"((b)[1]))

// ---- fast gate math: 1 MUFU per tanh ----
__device__ __forceinline__ float tanh_fast(float x) {
    float y;
    asm("tanh.approx.f32 %0, %1;" : "=f"(y) : "f"(x));
    return y;
}
__device__ __forceinline__ float sigmoid_fast(float x) {
    return fmaf(0.5f, tanh_fast(0.5f * x), 0.5f);
}

// =====================================================================
// Combined prep kernel (single launch):
//  blocks [0, NBA)            : A = concat(x1,x2) -> fp16
//  blocks [NBA, NBA+NBW1)     : W1 transpose+reorder -> fp16
//  blocks [.., +NBW2)         : W2 transpose -> fp16
//  last block                 : head weights -> MMA B-fragment order
// =====================================================================
#define NBA   (NB * (KDIM / 4) / 256)     // 16384
#define NBW1  ((KDIM * N1) / 256)         // 2304
#define NBW2  ((G1U * 48 + 255) / 256)    // 72
#define NPREP (NBA + NBW1 + NBW2 + 1)

__global__ __launch_bounds__(256)
void prep_kernel(const float* __restrict__ x1, const float* __restrict__ x2,
                 const float* __restrict__ W1, const float* __restrict__ W2,
                 const float* __restrict__ hw1, const float* __restrict__ hw2)
{
    const int b = blockIdx.x;
    const int t = threadIdx.x;
    if (b < NBA) {
        size_t i4 = (size_t)b * 256 + t;
        int m  = (int)(i4 >> 7);
        int c4 = ((int)i4 & 127) * 4;
        float4 v;
        if (c4 < IN1) v = *(const float4*)(x1 + (size_t)m * IN1 + c4);
        else          v = *(const float4*)(x2 + (size_t)m * IN2 + (c4 - IN1));
        size_t o = (size_t)m * KDIM + c4;
        *(__half2*)&g_Ah[o]     = __floats2half2_rn(v.x, v.y);
        *(__half2*)&g_Ah[o + 2] = __floats2half2_rn(v.z, v.w);
    } else if (b < NBA + NBW1) {
        int idx = (b - NBA) * 256 + t;      // < 589824
        int k = idx / N1, c = idx % N1;
        int g = c / G1U, j = c % G1U;
        int n = (j >> 4) * 48 + g * 16 + (j & 15);
        g_Bh[(size_t)n * KDIM + k] = __float2half_rn(W1[idx]);
    } else if (b < NBA + NBW1 + NBW2) {
        int idx = (b - NBA - NBW1) * 256 + t;
        if (idx < G1U * 48) {
            int k = idx / 48, c = idx % 48;
            g_B2[(size_t)c * G1U + k] = __float2half_rn(W2[idx]);
        }
    } else {
#pragma unroll
        for (int i = t; i < 1024; i += 256) {
            int tt = i >> 5, lane = i & 31;
            int k0 = (lane & 3) * 2;
            int n  = tt * 8 + (lane >> 2);
            __half2 p10 = __floats2half2_rn(hw1[k0 * NLEV + n],       hw1[(k0 + 1) * NLEV + n]);
            __half2 p11 = __floats2half2_rn(hw1[(k0 + 8) * NLEV + n], hw1[(k0 + 9) * NLEV + n]);
            __half2 p20 = __floats2half2_rn(hw2[k0 * NLEV + n],       hw2[(k0 + 1) * NLEV + n]);
            __half2 p21 = __floats2half2_rn(hw2[(k0 + 8) * NLEV + n], hw2[(k0 + 9) * NLEV + n]);
            g_Wf1[2 * i]     = *(u32*)&p10;
            g_Wf1[2 * i + 1] = *(u32*)&p11;
            g_Wf2[2 * i]     = *(u32*)&p20;
            g_Wf2[2 * i + 1] = *(u32*)&p21;
        }
    }
}

// =====================================================================
// GEMM1: h1 = GRU1(A, h=0).  fp16 single-pass HMMA.
// CTA = 192 thr (6 warps of 64x48) -> tile 192 x 96.  K: 8 tiles of 64.
// 3-stage cp.async (R6 one-barrier protocol), 2 CTAs/SM = 12 warps/SM.
// LDS demand 0.073 B/MAC -> crossbar below tensor demand.
// =====================================================================
#define G1_STAGE  36864            // 24KB A + 12KB B
#define G1_OFFB   24576
#define G1_NSTG   3
#define G1_BIAS   (G1_NSTG * G1_STAGE) // 110592
#define G1_SMEM   (G1_BIAS + 512)

__device__ __forceinline__ void load_stage_g1(u32 sb, int s, int kt, int m0, int nb, int tid)
{
    const int k0 = kt * 64;
    const u32 base = sb + s * G1_STAGE;
    const char* Ap = (const char*)g_Ah;
    const char* Bp = (const char*)g_Bh;
    // A tile: 192 rows x 128B = 1536 chunks of 16B, 192 threads -> 8 each
#pragma unroll
    for (int i = 0; i < 8; ++i) {
        int c = tid + i * 192;
        int row = c >> 3, cb = c & 7;
        u32 dst = base + swz(row * 128 + cb * 16);
        const char* src = Ap + (size_t)(m0 + row) * (KDIM * 2) + k0 * 2 + cb * 16;
        CP_ASYNC16(dst, src);
    }
    // B tile: 96 rows x 128B = 768 chunks -> 4 each
#pragma unroll
    for (int i = 0; i < 4; ++i) {
        int c = tid + i * 192;
        int row = c >> 3, cb = c & 7;
        u32 dst = base + G1_OFFB + swz(row * 128 + cb * 16);
        const char* src = Bp + (size_t)(nb * 96 + row) * (KDIM * 2) + k0 * 2 + cb * 16;
        CP_ASYNC16(dst, src);
    }
}

__global__ __launch_bounds__(192, 2)
void gemm1_mma_kernel(const float* __restrict__ bias)
{
    extern __shared__ char smem[];
    const u32 sb = smem_u32(smem);
    const int tid  = threadIdx.x;
    const int warp = tid >> 5, lane = tid & 31;
    const int wm = warp >> 1;         // 0..2 : m block 64*wm
    const int wn = warp & 1;          // 0..1 : n block 48*wn
    const int nb = blockIdx.x;        // 0..11  (32-unit block)
    const int m0 = blockIdx.y * 192;

    float* czs  = (float*)(smem + G1_BIAS);
    float* crs  = czs + 32;
    float* ch0s = czs + 64;
    float* ch1s = czs + 96;
    if (tid < 32) {
        int j = nb * 32 + tid;
        czs[tid]  = bias[j]         + bias[N1 + j];
        crs[tid]  = bias[G1U + j]   + bias[N1 + G1U + j];
        ch0s[tid] = bias[2 * G1U + j];
        ch1s[tid] = bias[N1 + 2 * G1U + j];
    }

    float acc[4][6][4];
#pragma unroll
    for (int mi = 0; mi < 4; ++mi)
#pragma unroll
        for (int ni = 0; ni < 6; ++ni)
#pragma unroll
            for (int e = 0; e < 4; ++e) acc[mi][ni][e] = 0.f;

    const int a_row = 64 * wm + (lane & 15);
    const int a_kb  = (lane & 16) ? 16 : 0;
    const int b_row = 48 * wn + (lane & 7) + ((lane & 16) ? 8 : 0);
    const int b_kb  = (lane & 8) ? 16 : 0;

    load_stage_g1(sb, 0, 0, m0, nb, tid); CP_COMMIT();
    load_stage_g1(sb, 1, 1, m0, nb, tid); CP_COMMIT();

    for (int kt = 0; kt < 8; ++kt) {
        const int s = kt % G1_NSTG;
        CP_WAIT1();
        __syncthreads();
        if (kt + 2 < 8) load_stage_g1(sb, (kt + 2) % G1_NSTG, kt + 2, m0, nb, tid);
        CP_COMMIT();

        const u32 abase = sb + s * G1_STAGE;
        const u32 bbase = abase + G1_OFFB;
#pragma unroll
        for (int ks = 0; ks < 4; ++ks) {
            u32 af[4][4], bf[3][4];
#pragma unroll
            for (int mi = 0; mi < 4; ++mi) {
                u32 ad = abase + swz((u32)(a_row + mi * 16) * 128 + ks * 32 + a_kb);
                LDSM_X4(af[mi][0], af[mi][1], af[mi][2], af[mi][3], ad);
            }
#pragma unroll
            for (int bi = 0; bi < 3; ++bi) {
                u32 bd = bbase + swz((u32)(b_row + bi * 16) * 128 + ks * 32 + b_kb);
                LDSM_X4(bf[bi][0], bf[bi][1], bf[bi][2], bf[bi][3], bd);
            }
#pragma unroll
            for (int mi = 0; mi < 4; ++mi)
#pragma unroll
                for (int bi = 0; bi < 3; ++bi) {
                    MMA16816(acc[mi][2 * bi],     af[mi], (&bf[bi][0]));
                    MMA16816(acc[mi][2 * bi + 1], af[mi], (&bf[bi][2]));
                }
        }
    }

    // ---- fused GRU epilogue (fast gates) ----
    const int qr = lane >> 2, qc = lane & 3;
#pragma unroll
    for (int mi = 0; mi < 4; ++mi) {
#pragma unroll
        for (int nip = 0; nip < 2; ++nip) {
            const int ul = wn * 16 + 8 * nip + 2 * qc;
            const int j0 = nb * 32 + ul;
            const float cz0 = czs[ul],  cz1 = czs[ul + 1];
            const float cr0 = crs[ul],  cr1 = crs[ul + 1];
            const float c00 = ch0s[ul], c01 = ch0s[ul + 1];
            const float c10 = ch1s[ul], c11 = ch1s[ul + 1];
            const float* az = acc[mi][nip];
            const float* ar = acc[mi][nip + 2];
            const float* ah = acc[mi][nip + 4];
#pragma unroll
            for (int half = 0; half < 2; ++half) {
                const int row = m0 + 64 * wm + 16 * mi + qr + half * 8;
                float z0 = sigmoid_fast(az[2 * half]     + cz0);
                float z1 = sigmoid_fast(az[2 * half + 1] + cz1);
                float r0 = sigmoid_fast(ar[2 * half]     + cr0);
                float r1 = sigmoid_fast(ar[2 * half + 1] + cr1);
                float h0 = tanh_fast(ah[2 * half]     + c00 + r0 * c10);
                float h1 = tanh_fast(ah[2 * half + 1] + c01 + r1 * c11);
                *(__half2*)&g_h1h[(size_t)row * G1U + j0] =
                    __floats2half2_rn((1.f - z0) * h0, (1.f - z1) * h1);
            }
        }
    }
}

// =====================================================================
// GEMM2: h2 = GRU2(h1, h=0) -> fp16 g_h2h.
// =====================================================================
#define G2_STAGE  22528
#define G2_OFFB   16384
#define G2_BIAS   (3 * G2_STAGE) // 67584
#define G2_SMEM   (G2_BIAS + 512)

__device__ __forceinline__ void load_stage_g2(u32 sb, int s, int kt, int m0, int tid)
{
    const int k0 = kt * 64;
    const u32 base = sb + s * G2_STAGE;
    const char* Ap = (const char*)g_h1h;
    const char* Bp = (const char*)g_B2;
#pragma unroll
    for (int i = 0; i < 4; ++i) {
        int c = tid + i * 256;              // 0..1023
        int row = c >> 3, cb = c & 7;
        u32 dst = base + swz(row * 128 + cb * 16);
        const char* src = Ap + (size_t)(m0 + row) * (G1U * 2) + k0 * 2 + cb * 16;
        CP_ASYNC16(dst, src);
    }
#pragma unroll
    for (int i = 0; i < 2; ++i) {
        int c = tid + i * 256;
        if (c < 384) {
            int row = c >> 3, cb = c & 7;
            u32 dst = base + G2_OFFB + swz(row * 128 + cb * 16);
            const char* src = Bp + (size_t)row * (G1U * 2) + k0 * 2 + cb * 16;
            CP_ASYNC16(dst, src);
        }
    }
}

__global__ __launch_bounds__(256, 2)
void gemm2_mma_kernel(const float* __restrict__ bias)
{
    extern __shared__ char smem[];
    const u32 sb = smem_u32(smem);
    const int tid  = threadIdx.x;
    const int warp = tid >> 5, lane = tid & 31;
    const int m0 = blockIdx.x * 128;

    float* czs  = (float*)(smem + G2_BIAS);
    float* crs  = czs + 16;
    float* ch0s = czs + 32;
    float* ch1s = czs + 48;
    if (tid < 16) {
        czs[tid]  = bias[tid]      + bias[48 + tid];
        crs[tid]  = bias[16 + tid] + bias[64 + tid];
        ch0s[tid] = bias[32 + tid];
        ch1s[tid] = bias[80 + tid];
    }

    float acc[6][4];
#pragma unroll
    for (int ni = 0; ni < 6; ++ni)
#pragma unroll
        for (int e = 0; e < 4; ++e) acc[ni][e] = 0.f;

    const int a_row = 16 * warp + (lane & 15);
    const int a_kb  = (lane & 16) ? 16 : 0;
    const int b_row = (lane & 7) + ((lane & 16) ? 8 : 0);
    const int b_kb  = (lane & 8) ? 16 : 0;

    load_stage_g2(sb, 0, 0, m0, tid); CP_COMMIT();
    load_stage_g2(sb, 1, 1, m0, tid); CP_COMMIT();

    for (int kt = 0; kt < 6; ++kt) {
        const int s = kt % 3;
        CP_WAIT1();
        __syncthreads();
        if (kt + 2 < 6) load_stage_g2(sb, (kt + 2) % 3, kt + 2, m0, tid);
        CP_COMMIT();

        const u32 abase = sb + s * G2_STAGE;
        const u32 bbase = abase + G2_OFFB;
#pragma unroll
        for (int ks = 0; ks < 4; ++ks) {
            u32 af[4], bf[3][4];
            u32 ad = abase + swz((u32)a_row * 128 + ks * 32 + a_kb);
            LDSM_X4(af[0], af[1], af[2], af[3], ad);
#pragma unroll
            for (int bi = 0; bi < 3; ++bi) {
                u32 bd = bbase + swz((u32)(b_row + bi * 16) * 128 + ks * 32 + b_kb);
                LDSM_X4(bf[bi][0], bf[bi][1], bf[bi][2], bf[bi][3], bd);
            }
#pragma unroll
            for (int bi = 0; bi < 3; ++bi) {
                MMA16816(acc[2 * bi],     af, (&bf[bi][0]));
                MMA16816(acc[2 * bi + 1], af, (&bf[bi][2]));
            }
        }
    }

    const int qr = lane >> 2, qc = lane & 3;
#pragma unroll
    for (int nip = 0; nip < 2; ++nip) {
        const int u0 = 8 * nip + 2 * qc;
        const float cz0 = czs[u0],  cz1 = czs[u0 + 1];
        const float cr0 = crs[u0],  cr1 = crs[u0 + 1];
        const float c00 = ch0s[u0], c01 = ch0s[u0 + 1];
        const float c10 = ch1s[u0], c11 = ch1s[u0 + 1];
        const float* az = acc[nip];
        const float* ar = acc[nip + 2];
        const float* ah = acc[nip + 4];
#pragma unroll
        for (int half = 0; half < 2; ++half) {
            const int row = m0 + 16 * warp + qr + half * 8;
            float z0 = sigmoid_fast(az[2 * half]     + cz0);
            float z1 = sigmoid_fast(az[2 * half + 1] + cz1);
            float r0 = sigmoid_fast(ar[2 * half]     + cr0);
            float r1 = sigmoid_fast(ar[2 * half + 1] + cr1);
            float h0 = tanh_fast(ah[2 * half]     + c00 + r0 * c10);
            float h1 = tanh_fast(ah[2 * half + 1] + c01 + r1 * c11);
            *(__half2*)&g_h2h[(size_t)row * G2U + u0] =
                __floats2half2_rn((1.f - z0) * h0, (1.f - z1) * h1);
        }
    }
}

// =====================================================================
// HEAD via HMMA: per warp, 16 rows. Logits in regs, quad-shfl softmax.
// =====================================================================
__global__ __launch_bounds__(256, 1)
void head_mma_kernel(const float* __restrict__ b1, const float* __restrict__ b2,
                     const float* __restrict__ gv1, const float* __restrict__ gv2,
                     float* __restrict__ out)
{
    __shared__ u32 Wf1s[2048], Wf2s[2048];
    __shared__ float b1s[NLEV], b2s[NLEV], g1s[NLEV], g2s[NLEV];

    const int t = threadIdx.x;
    for (int i = t; i < 2048; i += 256) { Wf1s[i] = g_Wf1[i]; Wf2s[i] = g_Wf2[i]; }
    b1s[t] = b1[t]; b2s[t] = b2[t]; g1s[t] = gv1[t]; g2s[t] = gv2[t];
    __syncthreads();

    const int warp = t >> 5, lane = t & 31;
    const int qr = lane >> 2, qc = lane & 3;
    const int rbase = blockIdx.x * 128 + warp * 16;

    const __half* h2p = g_h2h + (size_t)rbase * G2U;
    u32 a[4];
    a[0] = *(const u32*)&h2p[qr * G2U + 2 * qc];
    a[1] = *(const u32*)&h2p[(qr + 8) * G2U + 2 * qc];
    a[2] = *(const u32*)&h2p[qr * G2U + 2 * qc + 8];
    a[3] = *(const u32*)&h2p[(qr + 8) * G2U + 2 * qc + 8];

    float v[32][4];
    float mx0 = -1e30f, mx1 = -1e30f;
#pragma unroll
    for (int tt = 0; tt < 32; ++tt) {
        const int fi = (tt * 32 + lane) * 2;
        u32 bw1[2] = { Wf1s[fi], Wf1s[fi + 1] };
        u32 bw2[2] = { Wf2s[fi], Wf2s[fi + 1] };
        const int l = tt * 8 + 2 * qc;
        const float B1x = b1s[l], B1y = b1s[l + 1];
        const float B2x = b2s[l], B2y = b2s[l + 1];
        const float G1x = g1s[l], G1y = g1s[l + 1];
        const float G2x = g2s[l], G2y = g2s[l + 1];
        float d[4] = { B1x, B1y, B1x, B1y };
        float e[4] = { B2x, B2y, B2x, B2y };
        MMA16816(d, a, bw1);
        MMA16816(e, a, bw2);
        v[tt][0] = G1x * tanh_fast(d[0]) + G2x * tanh_fast(e[0]);
        v[tt][1] = G1y * tanh_fast(d[1]) + G2y * tanh_fast(e[1]);
        v[tt][2] = G1x * tanh_fast(d[2]) + G2x * tanh_fast(e[2]);
        v[tt][3] = G1y * tanh_fast(d[3]) + G2y * tanh_fast(e[3]);
        mx0 = fmaxf(mx0, fmaxf(v[tt][0], v[tt][1]));
        mx1 = fmaxf(mx1, fmaxf(v[tt][2], v[tt][3]));
    }
    mx0 = fmaxf(mx0, __shfl_xor_sync(0xffffffffu, mx0, 1));
    mx0 = fmaxf(mx0, __shfl_xor_sync(0xffffffffu, mx0, 2));
    mx1 = fmaxf(mx1, __shfl_xor_sync(0xffffffffu, mx1, 1));
    mx1 = fmaxf(mx1, __shfl_xor_sync(0xffffffffu, mx1, 2));

    float s0 = 0.f, s1 = 0.f;
#pragma unroll
    for (int tt = 0; tt < 32; ++tt) {
        v[tt][0] = __expf(v[tt][0] - mx0);
        v[tt][1] = __expf(v[tt][1] - mx0);
        v[tt][2] = __expf(v[tt][2] - mx1);
        v[tt][3] = __expf(v[tt][3] - mx1);
        s0 += v[tt][0] + v[tt][1];
        s1 += v[tt][2] + v[tt][3];
    }
    s0 += __shfl_xor_sync(0xffffffffu, s0, 1);
    s0 += __shfl_xor_sync(0xffffffffu, s0, 2);
    s1 += __shfl_xor_sync(0xffffffffu, s1, 1);
    s1 += __shfl_xor_sync(0xffffffffu, s1, 2);
    const float i0 = __fdividef(1.f, s0);
    const float i1 = __fdividef(1.f, s1);

    float* o0 = out + (size_t)(rbase + qr) * NLEV;
    float* o1 = out + (size_t)(rbase + qr + 8) * NLEV;
#pragma unroll
    for (int tt = 0; tt < 32; ++tt) {
        const int l = tt * 8 + 2 * qc;
        *(float2*)&o0[l] = make_float2(v[tt][0] * i0, v[tt][1] * i0);
        *(float2*)&o1[l] = make_float2(v[tt][2] * i1, v[tt][3] * i1);
    }
}

// =====================================================================
extern "C" void kernel_launch(void* const* d_in, const int* in_sizes, int n_in,
                              void* d_out, int out_size)
{
    const float* x1   = (const float*)d_in[0];
    const float* x2   = (const float*)d_in[1];
    const float* g1k  = (const float*)d_in[2];
    const float* g1b  = (const float*)d_in[4];
    const float* g2k  = (const float*)d_in[5];
    const float* g2b  = (const float*)d_in[7];
    const float* fw1  = (const float*)d_in[8];
    const float* fb1  = (const float*)d_in[9];
    const float* fw2  = (const float*)d_in[10];
    const float* fb2  = (const float*)d_in[11];
    const float* fg1  = (const float*)d_in[12];
    const float* fg2  = (const float*)d_in[13];
    float* out = (float*)d_out;

    cudaFuncSetAttribute(gemm1_mma_kernel,
                         cudaFuncAttributeMaxDynamicSharedMemorySize, G1_SMEM);
    cudaFuncSetAttribute(gemm2_mma_kernel,
                         cudaFuncAttributeMaxDynamicSharedMemorySize, G2_SMEM);

    prep_kernel<<<NPREP, 256>>>(x1, x2, g1k, g2k, fw1, fw2);
    gemm1_mma_kernel<<<dim3(12, MPAD / 192), 192, G1_SMEM>>>(g1b);
    gemm2_mma_kernel<<<NB / 128, 256, G2_SMEM>>>(g2b);
    head_mma_kernel<<<NB / 128, 256>>>(fb1, fb2, fg1, fg2, out);
}

// round 14
// speedup vs baseline: 1.1268x; 1.1268x over previous
#include <cuda_runtime.h>
#include <cuda_fp16.h>
#include <cstdint>

// ---------------- problem constants ----------------
#define NB     65536
#define IN1    384
#define IN2    128
#define KDIM   512
#define G1U    384
#define N1     1152
#define G2U    16
#define NLEV   256

typedef unsigned long long u64;
typedef unsigned int u32;

// ---------------- device scratch ----------------
__device__ __half g_Ah[(size_t)NB * KDIM];     // fp16 concat(x1,x2)
__device__ __half g_Bh[(size_t)N1 * KDIM];     // reordered+transposed W1
__device__ __half g_h1h[(size_t)NB * G1U];     // fp16 h1
__device__ __half g_B2[(size_t)48 * G1U];      // transposed W2
__device__ __half g_h2h[(size_t)NB * G2U];     // fp16 h2
__device__ u32    g_Wf1[2048];                 // head W1 in MMA B-fragment order
__device__ u32    g_Wf2[2048];                 // head W2 in MMA B-fragment order

// ---------------- helpers ----------------
__device__ __forceinline__ u32 smem_u32(const void* p) {
    u32 a;
    asm("{ .reg .u64 t; cvta.to.shared.u64 t, %1; cvt.u32.u64 %0, t; }" : "=r"(a) : "l"(p));
    return a;
}
__device__ __forceinline__ u32 swz(u32 x) { return x ^ ((x >> 3) & 0x70); }

#define CP_ASYNC16(dst, src) \
    asm volatile("cp.async.cg.shared.global [%0], [%1], 16;" :: "r"(dst), "l"(src) : "memory")
#define CP_COMMIT() asm volatile("cp.async.commit_group;" ::: "memory")
#define CP_WAIT1()  asm volatile("cp.async.wait_group 1;" ::: "memory")

#define LDSM_X4(r0, r1, r2, r3, addr) \
    asm volatile("ldmatrix.sync.aligned.m8n8.x4.shared.b16 {%0,%1,%2,%3}, [%4];" \
        : "=r"(r0), "=r"(r1), "=r"(r2), "=r"(r3) : "r"(addr))

#define MMA16816(d, a, b) \
    asm volatile("mma.sync.aligned.m16n8k16.row.col.f32.f16.f16.f32 " \
        "{%0,%1,%2,%3},{%4,%5,%6,%7},{%8,%9},{%0,%1,%2,%3};" \
        : "+f"((d)[0]), "+f"((d)[1]), "+f"((d)[2]), "+f"((d)[3]) \
        : "r"((a)[0]), "r"((a)[1]), "r"((a)[2]), "r"((a)[3]), "r"((b)[0]), "r"((b)[1]))

// ---- fast gate math: 1 MUFU per tanh ----
__device__ __forceinline__ float tanh_fast(float x) {
    float y;
    asm("tanh.approx.f32 %0, %1;" : "=f"(y) : "f"(x));
    return y;
}
__device__ __forceinline__ float sigmoid_fast(float x) {
    return fmaf(0.5f, tanh_fast(0.5f * x), 0.5f);
}

// =====================================================================
// Combined prep kernel (single launch)
// =====================================================================
#define NBA   (NB * (KDIM / 4) / 256)     // 16384
#define NBW1  ((KDIM * N1) / 256)         // 2304
#define NBW2  ((G1U * 48 + 255) / 256)    // 72
#define NPREP (NBA + NBW1 + NBW2 + 1)

__global__ __launch_bounds__(256)
void prep_kernel(const float* __restrict__ x1, const float* __restrict__ x2,
                 const float* __restrict__ W1, const float* __restrict__ W2,
                 const float* __restrict__ hw1, const float* __restrict__ hw2)
{
    const int b = blockIdx.x;
    const int t = threadIdx.x;
    if (b < NBA) {
        size_t i4 = (size_t)b * 256 + t;
        int m  = (int)(i4 >> 7);
        int c4 = ((int)i4 & 127) * 4;
        float4 v;
        if (c4 < IN1) v = *(const float4*)(x1 + (size_t)m * IN1 + c4);
        else          v = *(const float4*)(x2 + (size_t)m * IN2 + (c4 - IN1));
        size_t o = (size_t)m * KDIM + c4;
        *(__half2*)&g_Ah[o]     = __floats2half2_rn(v.x, v.y);
        *(__half2*)&g_Ah[o + 2] = __floats2half2_rn(v.z, v.w);
    } else if (b < NBA + NBW1) {
        int idx = (b - NBA) * 256 + t;      // < 589824
        int k = idx / N1, c = idx % N1;
        int g = c / G1U, j = c % G1U;
        int n = (j >> 4) * 48 + g * 16 + (j & 15);
        g_Bh[(size_t)n * KDIM + k] = __float2half_rn(W1[idx]);
    } else if (b < NBA + NBW1 + NBW2) {
        int idx = (b - NBA - NBW1) * 256 + t;
        if (idx < G1U * 48) {
            int k = idx / 48, c = idx % 48;
            g_B2[(size_t)c * G1U + k] = __float2half_rn(W2[idx]);
        }
    } else {
#pragma unroll
        for (int i = t; i < 1024; i += 256) {
            int tt = i >> 5, lane = i & 31;
            int k0 = (lane & 3) * 2;
            int n  = tt * 8 + (lane >> 2);
            __half2 p10 = __floats2half2_rn(hw1[k0 * NLEV + n],       hw1[(k0 + 1) * NLEV + n]);
            __half2 p11 = __floats2half2_rn(hw1[(k0 + 8) * NLEV + n], hw1[(k0 + 9) * NLEV + n]);
            __half2 p20 = __floats2half2_rn(hw2[k0 * NLEV + n],       hw2[(k0 + 1) * NLEV + n]);
            __half2 p21 = __floats2half2_rn(hw2[(k0 + 8) * NLEV + n], hw2[(k0 + 9) * NLEV + n]);
            g_Wf1[2 * i]     = *(u32*)&p10;
            g_Wf1[2 * i + 1] = *(u32*)&p11;
            g_Wf2[2 * i]     = *(u32*)&p20;
            g_Wf2[2 * i + 1] = *(u32*)&p21;
        }
    }
}

// =====================================================================
// GEMM1: h1 = GRU1(A, h=0).  fp16 single-pass HMMA.  (R12 champion, frozen)
// CTA tile 128 x 96; 8 warps of 32x48.  K = 512 -> 8 tiles of 64.
// 3-stage cp.async, one barrier per k-tile, 2 CTAs/SM, fast gates.
// =====================================================================
#define G1_STAGE  28672            // 16KB A + 12KB B
#define G1_OFFB   16384
#define G1_NSTG   3
#define G1_BIAS   (G1_NSTG * G1_STAGE) // 86016
#define G1_SMEM   (G1_BIAS + 512)

__device__ __forceinline__ void load_stage_g1(u32 sb, int s, int kt, int m0, int nb, int tid)
{
    const int k0 = kt * 64;
    const u32 base = sb + s * G1_STAGE;
    const char* Ap = (const char*)g_Ah;
    const char* Bp = (const char*)g_Bh;
#pragma unroll
    for (int i = 0; i < 4; ++i) {
        int c = tid + i * 256;              // 0..1023
        int row = c >> 3, cb = c & 7;
        u32 dst = base + swz(row * 128 + cb * 16);
        const char* src = Ap + (size_t)(m0 + row) * (KDIM * 2) + k0 * 2 + cb * 16;
        CP_ASYNC16(dst, src);
    }
#pragma unroll
    for (int i = 0; i < 3; ++i) {
        int c = tid + i * 256;              // 0..767
        int row = c >> 3, cb = c & 7;
        u32 dst = base + G1_OFFB + swz(row * 128 + cb * 16);
        const char* src = Bp + (size_t)(nb * 96 + row) * (KDIM * 2) + k0 * 2 + cb * 16;
        CP_ASYNC16(dst, src);
    }
}

__global__ __launch_bounds__(256, 2)
void gemm1_mma_kernel(const float* __restrict__ bias)
{
    extern __shared__ char smem[];
    const u32 sb = smem_u32(smem);
    const int tid  = threadIdx.x;
    const int warp = tid >> 5, lane = tid & 31;
    const int wm = warp & 3;
    const int wn = warp >> 2;
    const int nb = blockIdx.x;
    const int m0 = blockIdx.y * 128;

    float* czs  = (float*)(smem + G1_BIAS);
    float* crs  = czs + 32;
    float* ch0s = czs + 64;
    float* ch1s = czs + 96;
    if (tid < 32) {
        int j = nb * 32 + tid;
        czs[tid]  = bias[j]         + bias[N1 + j];
        crs[tid]  = bias[G1U + j]   + bias[N1 + G1U + j];
        ch0s[tid] = bias[2 * G1U + j];
        ch1s[tid] = bias[N1 + 2 * G1U + j];
    }

    float acc[2][6][4];
#pragma unroll
    for (int mi = 0; mi < 2; ++mi)
#pragma unroll
        for (int ni = 0; ni < 6; ++ni)
#pragma unroll
            for (int e = 0; e < 4; ++e) acc[mi][ni][e] = 0.f;

    const int a_row = 32 * wm + (lane & 15);
    const int a_kb  = (lane & 16) ? 16 : 0;
    const int b_row = 48 * wn + (lane & 7) + ((lane & 16) ? 8 : 0);
    const int b_kb  = (lane & 8) ? 16 : 0;

    load_stage_g1(sb, 0, 0, m0, nb, tid); CP_COMMIT();
    load_stage_g1(sb, 1, 1, m0, nb, tid); CP_COMMIT();

    for (int kt = 0; kt < 8; ++kt) {
        const int s = kt % G1_NSTG;
        CP_WAIT1();
        __syncthreads();
        if (kt + 2 < 8) load_stage_g1(sb, (kt + 2) % G1_NSTG, kt + 2, m0, nb, tid);
        CP_COMMIT();

        const u32 abase = sb + s * G1_STAGE;
        const u32 bbase = abase + G1_OFFB;
#pragma unroll
        for (int ks = 0; ks < 4; ++ks) {
            u32 af[2][4], bf[3][4];
#pragma unroll
            for (int mi = 0; mi < 2; ++mi) {
                u32 ad = abase + swz((u32)(a_row + mi * 16) * 128 + ks * 32 + a_kb);
                LDSM_X4(af[mi][0], af[mi][1], af[mi][2], af[mi][3], ad);
            }
#pragma unroll
            for (int bi = 0; bi < 3; ++bi) {
                u32 bd = bbase + swz((u32)(b_row + bi * 16) * 128 + ks * 32 + b_kb);
                LDSM_X4(bf[bi][0], bf[bi][1], bf[bi][2], bf[bi][3], bd);
            }
#pragma unroll
            for (int mi = 0; mi < 2; ++mi)
#pragma unroll
                for (int bi = 0; bi < 3; ++bi) {
                    MMA16816(acc[mi][2 * bi],     af[mi], (&bf[bi][0]));
                    MMA16816(acc[mi][2 * bi + 1], af[mi], (&bf[bi][2]));
                }
        }
    }

    // ---- fused GRU epilogue (fast gates) ----
    const int qr = lane >> 2, qc = lane & 3;
#pragma unroll
    for (int mi = 0; mi < 2; ++mi) {
#pragma unroll
        for (int nip = 0; nip < 2; ++nip) {
            const int ul = wn * 16 + 8 * nip + 2 * qc;
            const int j0 = nb * 32 + ul;
            const float cz0 = czs[ul],  cz1 = czs[ul + 1];
            const float cr0 = crs[ul],  cr1 = crs[ul + 1];
            const float c00 = ch0s[ul], c01 = ch0s[ul + 1];
            const float c10 = ch1s[ul], c11 = ch1s[ul + 1];
            const float* az = acc[mi][nip];
            const float* ar = acc[mi][nip + 2];
            const float* ah = acc[mi][nip + 4];
#pragma unroll
            for (int half = 0; half < 2; ++half) {
                const int row = m0 + 32 * wm + 16 * mi + qr + half * 8;
                float z0 = sigmoid_fast(az[2 * half]     + cz0);
                float z1 = sigmoid_fast(az[2 * half + 1] + cz1);
                float r0 = sigmoid_fast(ar[2 * half]     + cr0);
                float r1 = sigmoid_fast(ar[2 * half + 1] + cr1);
                float h0 = tanh_fast(ah[2 * half]     + c00 + r0 * c10);
                float h1 = tanh_fast(ah[2 * half + 1] + c01 + r1 * c11);
                *(__half2*)&g_h1h[(size_t)row * G1U + j0] =
                    __floats2half2_rn((1.f - z0) * h0, (1.f - z1) * h1);
            }
        }
    }
}

// =====================================================================
// GEMM2: h2 = GRU2(h1, h=0) -> fp16 g_h2h.  (R12, frozen)
// =====================================================================
#define G2_STAGE  22528
#define G2_OFFB   16384
#define G2_BIAS   (3 * G2_STAGE) // 67584
#define G2_SMEM   (G2_BIAS + 512)

__device__ __forceinline__ void load_stage_g2(u32 sb, int s, int kt, int m0, int tid)
{
    const int k0 = kt * 64;
    const u32 base = sb + s * G2_STAGE;
    const char* Ap = (const char*)g_h1h;
    const char* Bp = (const char*)g_B2;
#pragma unroll
    for (int i = 0; i < 4; ++i) {
        int c = tid + i * 256;
        int row = c >> 3, cb = c & 7;
        u32 dst = base + swz(row * 128 + cb * 16);
        const char* src = Ap + (size_t)(m0 + row) * (G1U * 2) + k0 * 2 + cb * 16;
        CP_ASYNC16(dst, src);
    }
#pragma unroll
    for (int i = 0; i < 2; ++i) {
        int c = tid + i * 256;
        if (c < 384) {
            int row = c >> 3, cb = c & 7;
            u32 dst = base + G2_OFFB + swz(row * 128 + cb * 16);
            const char* src = Bp + (size_t)row * (G1U * 2) + k0 * 2 + cb * 16;
            CP_ASYNC16(dst, src);
        }
    }
}

__global__ __launch_bounds__(256, 2)
void gemm2_mma_kernel(const float* __restrict__ bias)
{
    extern __shared__ char smem[];
    const u32 sb = smem_u32(smem);
    const int tid  = threadIdx.x;
    const int warp = tid >> 5, lane = tid & 31;
    const int m0 = blockIdx.x * 128;

    float* czs  = (float*)(smem + G2_BIAS);
    float* crs  = czs + 16;
    float* ch0s = czs + 32;
    float* ch1s = czs + 48;
    if (tid < 16) {
        czs[tid]  = bias[tid]      + bias[48 + tid];
        crs[tid]  = bias[16 + tid] + bias[64 + tid];
        ch0s[tid] = bias[32 + tid];
        ch1s[tid] = bias[80 + tid];
    }

    float acc[6][4];
#pragma unroll
    for (int ni = 0; ni < 6; ++ni)
#pragma unroll
        for (int e = 0; e < 4; ++e) acc[ni][e] = 0.f;

    const int a_row = 16 * warp + (lane & 15);
    const int a_kb  = (lane & 16) ? 16 : 0;
    const int b_row = (lane & 7) + ((lane & 16) ? 8 : 0);
    const int b_kb  = (lane & 8) ? 16 : 0;

    load_stage_g2(sb, 0, 0, m0, tid); CP_COMMIT();
    load_stage_g2(sb, 1, 1, m0, tid); CP_COMMIT();

    for (int kt = 0; kt < 6; ++kt) {
        const int s = kt % 3;
        CP_WAIT1();
        __syncthreads();
        if (kt + 2 < 6) load_stage_g2(sb, (kt + 2) % 3, kt + 2, m0, tid);
        CP_COMMIT();

        const u32 abase = sb + s * G2_STAGE;
        const u32 bbase = abase + G2_OFFB;
#pragma unroll
        for (int ks = 0; ks < 4; ++ks) {
            u32 af[4], bf[3][4];
            u32 ad = abase + swz((u32)a_row * 128 + ks * 32 + a_kb);
            LDSM_X4(af[0], af[1], af[2], af[3], ad);
#pragma unroll
            for (int bi = 0; bi < 3; ++bi) {
                u32 bd = bbase + swz((u32)(b_row + bi * 16) * 128 + ks * 32 + b_kb);
                LDSM_X4(bf[bi][0], bf[bi][1], bf[bi][2], bf[bi][3], bd);
            }
#pragma unroll
            for (int bi = 0; bi < 3; ++bi) {
                MMA16816(acc[2 * bi],     af, (&bf[bi][0]));
                MMA16816(acc[2 * bi + 1], af, (&bf[bi][2]));
            }
        }
    }

    const int qr = lane >> 2, qc = lane & 3;
#pragma unroll
    for (int nip = 0; nip < 2; ++nip) {
        const int u0 = 8 * nip + 2 * qc;
        const float cz0 = czs[u0],  cz1 = czs[u0 + 1];
        const float cr0 = crs[u0],  cr1 = crs[u0 + 1];
        const float c00 = ch0s[u0], c01 = ch0s[u0 + 1];
        const float c10 = ch1s[u0], c11 = ch1s[u0 + 1];
        const float* az = acc[nip];
        const float* ar = acc[nip + 2];
        const float* ah = acc[nip + 4];
#pragma unroll
        for (int half = 0; half < 2; ++half) {
            const int row = m0 + 16 * warp + qr + half * 8;
            float z0 = sigmoid_fast(az[2 * half]     + cz0);
            float z1 = sigmoid_fast(az[2 * half + 1] + cz1);
            float r0 = sigmoid_fast(ar[2 * half]     + cr0);
            float r1 = sigmoid_fast(ar[2 * half + 1] + cr1);
            float h0 = tanh_fast(ah[2 * half]     + c00 + r0 * c10);
            float h1 = tanh_fast(ah[2 * half + 1] + c01 + r1 * c11);
            *(__half2*)&g_h2h[(size_t)row * G2U + u0] =
                __floats2half2_rn((1.f - z0) * h0, (1.f - z1) * h1);
        }
    }
}

// =====================================================================
// HEAD v2: 2 warps per 16-row group, 16 n-tiles each (v regs halved),
// cross-warp softmax via smem. CTA = 128 thr, 3 CTAs/SM.
// =====================================================================
__global__ __launch_bounds__(128, 3)
void head_mma_kernel(const float* __restrict__ b1, const float* __restrict__ b2,
                     const float* __restrict__ gv1, const float* __restrict__ gv2,
                     float* __restrict__ out)
{
    __shared__ u32 Wf1s[2048], Wf2s[2048];
    __shared__ float b1s[NLEV], b2s[NLEV], g1s[NLEV], g2s[NLEV];
    __shared__ float redmax[2][2][2][8];   // [rowgrp][half][which][qr]
    __shared__ float redsum[2][2][2][8];

    const int t = threadIdx.x;
    for (int i = t; i < 2048; i += 128) { Wf1s[i] = g_Wf1[i]; Wf2s[i] = g_Wf2[i]; }
    for (int i = t; i < NLEV; i += 128) {
        b1s[i] = b1[i]; b2s[i] = b2[i]; g1s[i] = gv1[i]; g2s[i] = gv2[i];
    }
    __syncthreads();

    const int warp = t >> 5, lane = t & 31;
    const int rowgrp = warp >> 1;          // 0..1
    const int half   = warp & 1;           // tile half
    const int qr = lane >> 2, qc = lane & 3;
    const int rbase = blockIdx.x * 32 + rowgrp * 16;

    const __half* h2p = g_h2h + (size_t)rbase * G2U;
    u32 a[4];
    a[0] = *(const u32*)&h2p[qr * G2U + 2 * qc];
    a[1] = *(const u32*)&h2p[(qr + 8) * G2U + 2 * qc];
    a[2] = *(const u32*)&h2p[qr * G2U + 2 * qc + 8];
    a[3] = *(const u32*)&h2p[(qr + 8) * G2U + 2 * qc + 8];

    float v[16][4];
    float mx0 = -1e30f, mx1 = -1e30f;
#pragma unroll
    for (int tt = 0; tt < 16; ++tt) {
        const int tile = half * 16 + tt;
        const int fi = (tile * 32 + lane) * 2;
        u32 bw1[2] = { Wf1s[fi], Wf1s[fi + 1] };
        u32 bw2[2] = { Wf2s[fi], Wf2s[fi + 1] };
        const int l = tile * 8 + 2 * qc;
        const float B1x = b1s[l], B1y = b1s[l + 1];
        const float B2x = b2s[l], B2y = b2s[l + 1];
        const float G1x = g1s[l], G1y = g1s[l + 1];
        const float G2x = g2s[l], G2y = g2s[l + 1];
        float d[4] = { B1x, B1y, B1x, B1y };
        float e[4] = { B2x, B2y, B2x, B2y };
        MMA16816(d, a, bw1);
        MMA16816(e, a, bw2);
        v[tt][0] = G1x * tanh_fast(d[0]) + G2x * tanh_fast(e[0]);
        v[tt][1] = G1y * tanh_fast(d[1]) + G2y * tanh_fast(e[1]);
        v[tt][2] = G1x * tanh_fast(d[2]) + G2x * tanh_fast(e[2]);
        v[tt][3] = G1y * tanh_fast(d[3]) + G2y * tanh_fast(e[3]);
        mx0 = fmaxf(mx0, fmaxf(v[tt][0], v[tt][1]));
        mx1 = fmaxf(mx1, fmaxf(v[tt][2], v[tt][3]));
    }
    // quad (same-row) reduction, then cross-warp (half) via smem
    mx0 = fmaxf(mx0, __shfl_xor_sync(0xffffffffu, mx0, 1));
    mx0 = fmaxf(mx0, __shfl_xor_sync(0xffffffffu, mx0, 2));
    mx1 = fmaxf(mx1, __shfl_xor_sync(0xffffffffu, mx1, 1));
    mx1 = fmaxf(mx1, __shfl_xor_sync(0xffffffffu, mx1, 2));
    if (qc == 0) {
        redmax[rowgrp][half][0][qr] = mx0;
        redmax[rowgrp][half][1][qr] = mx1;
    }
    __syncthreads();
    mx0 = fmaxf(redmax[rowgrp][0][0][qr], redmax[rowgrp][1][0][qr]);
    mx1 = fmaxf(redmax[rowgrp][0][1][qr], redmax[rowgrp][1][1][qr]);

    float s0 = 0.f, s1 = 0.f;
#pragma unroll
    for (int tt = 0; tt < 16; ++tt) {
        v[tt][0] = __expf(v[tt][0] - mx0);
        v[tt][1] = __expf(v[tt][1] - mx0);
        v[tt][2] = __expf(v[tt][2] - mx1);
        v[tt][3] = __expf(v[tt][3] - mx1);
        s0 += v[tt][0] + v[tt][1];
        s1 += v[tt][2] + v[tt][3];
    }
    s0 += __shfl_xor_sync(0xffffffffu, s0, 1);
    s0 += __shfl_xor_sync(0xffffffffu, s0, 2);
    s1 += __shfl_xor_sync(0xffffffffu, s1, 1);
    s1 += __shfl_xor_sync(0xffffffffu, s1, 2);
    if (qc == 0) {
        redsum[rowgrp][half][0][qr] = s0;
        redsum[rowgrp][half][1][qr] = s1;
    }
    __syncthreads();
    const float i0 = __fdividef(1.f, redsum[rowgrp][0][0][qr] + redsum[rowgrp][1][0][qr]);
    const float i1 = __fdividef(1.f, redsum[rowgrp][0][1][qr] + redsum[rowgrp][1][1][qr]);

    float* o0 = out + (size_t)(rbase + qr) * NLEV;
    float* o1 = out + (size_t)(rbase + qr + 8) * NLEV;
#pragma unroll
    for (int tt = 0; tt < 16; ++tt) {
        const int l = (half * 16 + tt) * 8 + 2 * qc;
        *(float2*)&o0[l] = make_float2(v[tt][0] * i0, v[tt][1] * i0);
        *(float2*)&o1[l] = make_float2(v[tt][2] * i1, v[tt][3] * i1);
    }
}

// =====================================================================
extern "C" void kernel_launch(void* const* d_in, const int* in_sizes, int n_in,
                              void* d_out, int out_size)
{
    const float* x1   = (const float*)d_in[0];
    const float* x2   = (const float*)d_in[1];
    const float* g1k  = (const float*)d_in[2];
    const float* g1b  = (const float*)d_in[4];
    const float* g2k  = (const float*)d_in[5];
    const float* g2b  = (const float*)d_in[7];
    const float* fw1  = (const float*)d_in[8];
    const float* fb1  = (const float*)d_in[9];
    const float* fw2  = (const float*)d_in[10];
    const float* fb2  = (const float*)d_in[11];
    const float* fg1  = (const float*)d_in[12];
    const float* fg2  = (const float*)d_in[13];
    float* out = (float*)d_out;

    cudaFuncSetAttribute(gemm1_mma_kernel,
                         cudaFuncAttributeMaxDynamicSharedMemorySize, G1_SMEM);
    cudaFuncSetAttribute(gemm2_mma_kernel,
                         cudaFuncAttributeMaxDynamicSharedMemorySize, G2_SMEM);

    prep_kernel<<<NPREP, 256>>>(x1, x2, g1k, g2k, fw1, fw2);
    gemm1_mma_kernel<<<dim3(12, NB / 128), 256, G1_SMEM>>>(g1b);
    gemm2_mma_kernel<<<NB / 128, 256, G2_SMEM>>>(g2b);
    head_mma_kernel<<<NB / 32, 128>>>(fb1, fb2, fg1, fg2, out);
}

// round 15
// speedup vs baseline: 1.1859x; 1.0524x over previous
#include <cuda_runtime.h>
#include <cuda_fp16.h>
#include <cstdint>

// ---------------- problem constants ----------------
#define NB     65536
#define IN1    384
#define IN2    128
#define KDIM   512
#define G1U    384
#define N1     1152
#define G2U    16
#define NLEV   256

typedef unsigned long long u64;
typedef unsigned int u32;

// ---------------- device scratch ----------------
__device__ __half g_Ah[(size_t)NB * KDIM];     // fp16 concat(x1,x2)
__device__ __half g_Bh[(size_t)N1 * KDIM];     // reordered+transposed W1
__device__ __half g_h1h[(size_t)NB * G1U];     // fp16 h1
__device__ __half g_B2[(size_t)48 * G1U];      // transposed W2
__device__ __half g_h2h[(size_t)NB * G2U];     // fp16 h2
__device__ u32    g_Wf1[2048];                 // head W1 in MMA B-fragment order
__device__ u32    g_Wf2[2048];                 // head W2 in MMA B-fragment order

// ---------------- helpers ----------------
__device__ __forceinline__ u32 smem_u32(const void* p) {
    u32 a;
    asm("{ .reg .u64 t; cvta.to.shared.u64 t, %1; cvt.u32.u64 %0, t; }" : "=r"(a) : "l"(p));
    return a;
}
__device__ __forceinline__ u32 swz(u32 x) { return x ^ ((x >> 3) & 0x70); }

#define CP_ASYNC16(dst, src) \
    asm volatile("cp.async.cg.shared.global [%0], [%1], 16;" :: "r"(dst), "l"(src) : "memory")
#define CP_COMMIT() asm volatile("cp.async.commit_group;" ::: "memory")
#define CP_WAIT1()  asm volatile("cp.async.wait_group 1;" ::: "memory")

#define LDSM_X4(r0, r1, r2, r3, addr) \
    asm volatile("ldmatrix.sync.aligned.m8n8.x4.shared.b16 {%0,%1,%2,%3}, [%4];" \
        : "=r"(r0), "=r"(r1), "=r"(r2), "=r"(r3) : "r"(addr))

#define MMA16816(d, a, b) \
    asm volatile("mma.sync.aligned.m16n8k16.row.col.f32.f16.f16.f32 " \
        "{%0,%1,%2,%3},{%4,%5,%6,%7},{%8,%9},{%0,%1,%2,%3};" \
        : "+f"((d)[0]), "+f"((d)[1]), "+f"((d)[2]), "+f"((d)[3]) \
        : "r"((a)[0]), "r"((a)[1]), "r"((a)[2]), "r"((a)[3]), "r"((b)[0]), "r"((b)[1]))

// ---- fast gate math: 1 MUFU per tanh ----
__device__ __forceinline__ float tanh_fast(float x) {
    float y;
    asm("tanh.approx.f32 %0, %1;" : "=f"(y) : "f"(x));
    return y;
}
__device__ __forceinline__ float sigmoid_fast(float x) {
    return fmaf(0.5f, tanh_fast(0.5f * x), 0.5f);
}

// =====================================================================
// Combined prep kernel (single launch):
//  [0, NBA)       : A = concat(x1,x2) -> fp16, 32B-read/16B-write per thr
//  [NBA, +NTW1)   : W1 smem-tiled transpose+reorder -> fp16 (coalesced)
//  [.., +NBW2)    : W2 transpose -> fp16
//  last           : head weights -> MMA B-fragment order
// =====================================================================
#define NBA   (NB * (KDIM / 8) / 256)     // 16384
#define NTW1  ((N1 / 64) * (KDIM / 64))   // 18 * 8 = 144
#define NBW2  ((G1U * 48 + 255) / 256)    // 72
#define NPREP (NBA + NTW1 + NBW2 + 1)

__global__ __launch_bounds__(256)
void prep_kernel(const float* __restrict__ x1, const float* __restrict__ x2,
                 const float* __restrict__ W1, const float* __restrict__ W2,
                 const float* __restrict__ hw1, const float* __restrict__ hw2)
{
    const int b = blockIdx.x;
    const int t = threadIdx.x;
    if (b < NBA) {
        // A: 8 floats per thread -> 8 halves (one 16B store)
        size_t i8 = (size_t)b * 256 + t;            // over NB * 64
        int m  = (int)(i8 >> 6);
        int c8 = ((int)i8 & 63) * 8;
        const float4* s;
        if (c8 < IN1) s = (const float4*)(x1 + (size_t)m * IN1 + c8);
        else          s = (const float4*)(x2 + (size_t)m * IN2 + (c8 - IN1));
        float4 v0 = s[0], v1 = s[1];
        __half2 h0 = __floats2half2_rn(v0.x, v0.y);
        __half2 h1 = __floats2half2_rn(v0.z, v0.w);
        __half2 h2 = __floats2half2_rn(v1.x, v1.y);
        __half2 h3 = __floats2half2_rn(v1.z, v1.w);
        uint4 o;
        o.x = *(u32*)&h0; o.y = *(u32*)&h1; o.z = *(u32*)&h2; o.w = *(u32*)&h3;
        *(uint4*)&g_Ah[(size_t)m * KDIM + c8] = o;
    } else if (b < NBA + NTW1) {
        // W1 transpose: tile 64 k-rows x 64 c-cols through smem
        __shared__ __half sm[64][72];               // [c][k], padded
        const int tile = b - NBA;
        const int c0 = (tile % (N1 / 64)) * 64;
        const int k0 = (tile / (N1 / 64)) * 64;
        // load 64x64 fp32 coalesced: 1024 float4 chunks
#pragma unroll
        for (int i = 0; i < 4; ++i) {
            int idx = t + i * 256;                  // 0..1023
            int kr = idx >> 4, c4 = (idx & 15) * 4;
            float4 v = *(const float4*)(W1 + (size_t)(k0 + kr) * N1 + c0 + c4);
            sm[c4 + 0][kr] = __float2half_rn(v.x);
            sm[c4 + 1][kr] = __float2half_rn(v.y);
            sm[c4 + 2][kr] = __float2half_rn(v.z);
            sm[c4 + 3][kr] = __float2half_rn(v.w);
        }
        __syncthreads();
        // write out: thread -> (local c, k-chunk of 16): 32B coalesced-ish
        {
            int lc = t >> 2, kc = (t & 3) * 16;
            int c = c0 + lc;
            int g = c / G1U, j = c % G1U;
            int n = (j >> 4) * 48 + g * 16 + (j & 15);
            uint4 o0, o1;
            o0 = *(uint4*)&sm[lc][kc];
            o1 = *(uint4*)&sm[lc][kc + 8];
            uint4* dst = (uint4*)&g_Bh[(size_t)n * KDIM + k0 + kc];
            dst[0] = o0;
            dst[1] = o1;
        }
    } else if (b < NBA + NTW1 + NBW2) {
        int idx = (b - NBA - NTW1) * 256 + t;
        if (idx < G1U * 48) {
            int k = idx / 48, c = idx % 48;
            g_B2[(size_t)c * G1U + k] = __float2half_rn(W2[idx]);
        }
    } else {
#pragma unroll
        for (int i = t; i < 1024; i += 256) {
            int tt = i >> 5, lane = i & 31;
            int k0 = (lane & 3) * 2;
            int n  = tt * 8 + (lane >> 2);
            __half2 p10 = __floats2half2_rn(hw1[k0 * NLEV + n],       hw1[(k0 + 1) * NLEV + n]);
            __half2 p11 = __floats2half2_rn(hw1[(k0 + 8) * NLEV + n], hw1[(k0 + 9) * NLEV + n]);
            __half2 p20 = __floats2half2_rn(hw2[k0 * NLEV + n],       hw2[(k0 + 1) * NLEV + n]);
            __half2 p21 = __floats2half2_rn(hw2[(k0 + 8) * NLEV + n], hw2[(k0 + 9) * NLEV + n]);
            g_Wf1[2 * i]     = *(u32*)&p10;
            g_Wf1[2 * i + 1] = *(u32*)&p11;
            g_Wf2[2 * i]     = *(u32*)&p20;
            g_Wf2[2 * i + 1] = *(u32*)&p21;
        }
    }
}

// =====================================================================
// GEMM1: h1 = GRU1(A, h=0).  fp16 single-pass HMMA.  (R12 champion, frozen)
// =====================================================================
#define G1_STAGE  28672            // 16KB A + 12KB B
#define G1_OFFB   16384
#define G1_NSTG   3
#define G1_BIAS   (G1_NSTG * G1_STAGE) // 86016
#define G1_SMEM   (G1_BIAS + 512)

__device__ __forceinline__ void load_stage_g1(u32 sb, int s, int kt, int m0, int nb, int tid)
{
    const int k0 = kt * 64;
    const u32 base = sb + s * G1_STAGE;
    const char* Ap = (const char*)g_Ah;
    const char* Bp = (const char*)g_Bh;
#pragma unroll
    for (int i = 0; i < 4; ++i) {
        int c = tid + i * 256;              // 0..1023
        int row = c >> 3, cb = c & 7;
        u32 dst = base + swz(row * 128 + cb * 16);
        const char* src = Ap + (size_t)(m0 + row) * (KDIM * 2) + k0 * 2 + cb * 16;
        CP_ASYNC16(dst, src);
    }
#pragma unroll
    for (int i = 0; i < 3; ++i) {
        int c = tid + i * 256;              // 0..767
        int row = c >> 3, cb = c & 7;
        u32 dst = base + G1_OFFB + swz(row * 128 + cb * 16);
        const char* src = Bp + (size_t)(nb * 96 + row) * (KDIM * 2) + k0 * 2 + cb * 16;
        CP_ASYNC16(dst, src);
    }
}

__global__ __launch_bounds__(256, 2)
void gemm1_mma_kernel(const float* __restrict__ bias)
{
    extern __shared__ char smem[];
    const u32 sb = smem_u32(smem);
    const int tid  = threadIdx.x;
    const int warp = tid >> 5, lane = tid & 31;
    const int wm = warp & 3;
    const int wn = warp >> 2;
    const int nb = blockIdx.x;
    const int m0 = blockIdx.y * 128;

    float* czs  = (float*)(smem + G1_BIAS);
    float* crs  = czs + 32;
    float* ch0s = czs + 64;
    float* ch1s = czs + 96;
    if (tid < 32) {
        int j = nb * 32 + tid;
        czs[tid]  = bias[j]         + bias[N1 + j];
        crs[tid]  = bias[G1U + j]   + bias[N1 + G1U + j];
        ch0s[tid] = bias[2 * G1U + j];
        ch1s[tid] = bias[N1 + 2 * G1U + j];
    }

    float acc[2][6][4];
#pragma unroll
    for (int mi = 0; mi < 2; ++mi)
#pragma unroll
        for (int ni = 0; ni < 6; ++ni)
#pragma unroll
            for (int e = 0; e < 4; ++e) acc[mi][ni][e] = 0.f;

    const int a_row = 32 * wm + (lane & 15);
    const int a_kb  = (lane & 16) ? 16 : 0;
    const int b_row = 48 * wn + (lane & 7) + ((lane & 16) ? 8 : 0);
    const int b_kb  = (lane & 8) ? 16 : 0;

    load_stage_g1(sb, 0, 0, m0, nb, tid); CP_COMMIT();
    load_stage_g1(sb, 1, 1, m0, nb, tid); CP_COMMIT();

    for (int kt = 0; kt < 8; ++kt) {
        const int s = kt % G1_NSTG;
        CP_WAIT1();
        __syncthreads();
        if (kt + 2 < 8) load_stage_g1(sb, (kt + 2) % G1_NSTG, kt + 2, m0, nb, tid);
        CP_COMMIT();

        const u32 abase = sb + s * G1_STAGE;
        const u32 bbase = abase + G1_OFFB;
#pragma unroll
        for (int ks = 0; ks < 4; ++ks) {
            u32 af[2][4], bf[3][4];
#pragma unroll
            for (int mi = 0; mi < 2; ++mi) {
                u32 ad = abase + swz((u32)(a_row + mi * 16) * 128 + ks * 32 + a_kb);
                LDSM_X4(af[mi][0], af[mi][1], af[mi][2], af[mi][3], ad);
            }
#pragma unroll
            for (int bi = 0; bi < 3; ++bi) {
                u32 bd = bbase + swz((u32)(b_row + bi * 16) * 128 + ks * 32 + b_kb);
                LDSM_X4(bf[bi][0], bf[bi][1], bf[bi][2], bf[bi][3], bd);
            }
#pragma unroll
            for (int mi = 0; mi < 2; ++mi)
#pragma unroll
                for (int bi = 0; bi < 3; ++bi) {
                    MMA16816(acc[mi][2 * bi],     af[mi], (&bf[bi][0]));
                    MMA16816(acc[mi][2 * bi + 1], af[mi], (&bf[bi][2]));
                }
        }
    }

    const int qr = lane >> 2, qc = lane & 3;
#pragma unroll
    for (int mi = 0; mi < 2; ++mi) {
#pragma unroll
        for (int nip = 0; nip < 2; ++nip) {
            const int ul = wn * 16 + 8 * nip + 2 * qc;
            const int j0 = nb * 32 + ul;
            const float cz0 = czs[ul],  cz1 = czs[ul + 1];
            const float cr0 = crs[ul],  cr1 = crs[ul + 1];
            const float c00 = ch0s[ul], c01 = ch0s[ul + 1];
            const float c10 = ch1s[ul], c11 = ch1s[ul + 1];
            const float* az = acc[mi][nip];
            const float* ar = acc[mi][nip + 2];
            const float* ah = acc[mi][nip + 4];
#pragma unroll
            for (int half = 0; half < 2; ++half) {
                const int row = m0 + 32 * wm + 16 * mi + qr + half * 8;
                float z0 = sigmoid_fast(az[2 * half]     + cz0);
                float z1 = sigmoid_fast(az[2 * half + 1] + cz1);
                float r0 = sigmoid_fast(ar[2 * half]     + cr0);
                float r1 = sigmoid_fast(ar[2 * half + 1] + cr1);
                float h0 = tanh_fast(ah[2 * half]     + c00 + r0 * c10);
                float h1 = tanh_fast(ah[2 * half + 1] + c01 + r1 * c11);
                *(__half2*)&g_h1h[(size_t)row * G1U + j0] =
                    __floats2half2_rn((1.f - z0) * h0, (1.f - z1) * h1);
            }
        }
    }
}

// =====================================================================
// GEMM2: h2 = GRU2(h1, h=0) -> fp16 g_h2h.  (R12, frozen)
// =====================================================================
#define G2_STAGE  22528
#define G2_OFFB   16384
#define G2_BIAS   (3 * G2_STAGE) // 67584
#define G2_SMEM   (G2_BIAS + 512)

__device__ __forceinline__ void load_stage_g2(u32 sb, int s, int kt, int m0, int tid)
{
    const int k0 = kt * 64;
    const u32 base = sb + s * G2_STAGE;
    const char* Ap = (const char*)g_h1h;
    const char* Bp = (const char*)g_B2;
#pragma unroll
    for (int i = 0; i < 4; ++i) {
        int c = tid + i * 256;
        int row = c >> 3, cb = c & 7;
        u32 dst = base + swz(row * 128 + cb * 16);
        const char* src = Ap + (size_t)(m0 + row) * (G1U * 2) + k0 * 2 + cb * 16;
        CP_ASYNC16(dst, src);
    }
#pragma unroll
    for (int i = 0; i < 2; ++i) {
        int c = tid + i * 256;
        if (c < 384) {
            int row = c >> 3, cb = c & 7;
            u32 dst = base + G2_OFFB + swz(row * 128 + cb * 16);
            const char* src = Bp + (size_t)row * (G1U * 2) + k0 * 2 + cb * 16;
            CP_ASYNC16(dst, src);
        }
    }
}

__global__ __launch_bounds__(256, 2)
void gemm2_mma_kernel(const float* __restrict__ bias)
{
    extern __shared__ char smem[];
    const u32 sb = smem_u32(smem);
    const int tid  = threadIdx.x;
    const int warp = tid >> 5, lane = tid & 31;
    const int m0 = blockIdx.x * 128;

    float* czs  = (float*)(smem + G2_BIAS);
    float* crs  = czs + 16;
    float* ch0s = czs + 32;
    float* ch1s = czs + 48;
    if (tid < 16) {
        czs[tid]  = bias[tid]      + bias[48 + tid];
        crs[tid]  = bias[16 + tid] + bias[64 + tid];
        ch0s[tid] = bias[32 + tid];
        ch1s[tid] = bias[80 + tid];
    }

    float acc[6][4];
#pragma unroll
    for (int ni = 0; ni < 6; ++ni)
#pragma unroll
        for (int e = 0; e < 4; ++e) acc[ni][e] = 0.f;

    const int a_row = 16 * warp + (lane & 15);
    const int a_kb  = (lane & 16) ? 16 : 0;
    const int b_row = (lane & 7) + ((lane & 16) ? 8 : 0);
    const int b_kb  = (lane & 8) ? 16 : 0;

    load_stage_g2(sb, 0, 0, m0, tid); CP_COMMIT();
    load_stage_g2(sb, 1, 1, m0, tid); CP_COMMIT();

    for (int kt = 0; kt < 6; ++kt) {
        const int s = kt % 3;
        CP_WAIT1();
        __syncthreads();
        if (kt + 2 < 6) load_stage_g2(sb, (kt + 2) % 3, kt + 2, m0, tid);
        CP_COMMIT();

        const u32 abase = sb + s * G2_STAGE;
        const u32 bbase = abase + G2_OFFB;
#pragma unroll
        for (int ks = 0; ks < 4; ++ks) {
            u32 af[4], bf[3][4];
            u32 ad = abase + swz((u32)a_row * 128 + ks * 32 + a_kb);
            LDSM_X4(af[0], af[1], af[2], af[3], ad);
#pragma unroll
            for (int bi = 0; bi < 3; ++bi) {
                u32 bd = bbase + swz((u32)(b_row + bi * 16) * 128 + ks * 32 + b_kb);
                LDSM_X4(bf[bi][0], bf[bi][1], bf[bi][2], bf[bi][3], bd);
            }
#pragma unroll
            for (int bi = 0; bi < 3; ++bi) {
                MMA16816(acc[2 * bi],     af, (&bf[bi][0]));
                MMA16816(acc[2 * bi + 1], af, (&bf[bi][2]));
            }
        }
    }

    const int qr = lane >> 2, qc = lane & 3;
#pragma unroll
    for (int nip = 0; nip < 2; ++nip) {
        const int u0 = 8 * nip + 2 * qc;
        const float cz0 = czs[u0],  cz1 = czs[u0 + 1];
        const float cr0 = crs[u0],  cr1 = crs[u0 + 1];
        const float c00 = ch0s[u0], c01 = ch0s[u0 + 1];
        const float c10 = ch1s[u0], c11 = ch1s[u0 + 1];
        const float* az = acc[nip];
        const float* ar = acc[nip + 2];
        const float* ah = acc[nip + 4];
#pragma unroll
        for (int half = 0; half < 2; ++half) {
            const int row = m0 + 16 * warp + qr + half * 8;
            float z0 = sigmoid_fast(az[2 * half]     + cz0);
            float z1 = sigmoid_fast(az[2 * half + 1] + cz1);
            float r0 = sigmoid_fast(ar[2 * half]     + cr0);
            float r1 = sigmoid_fast(ar[2 * half + 1] + cr1);
            float h0 = tanh_fast(ah[2 * half]     + c00 + r0 * c10);
            float h1 = tanh_fast(ah[2 * half + 1] + c01 + r1 * c11);
            *(__half2*)&g_h2h[(size_t)row * G2U + u0] =
                __floats2half2_rn((1.f - z0) * h0, (1.f - z1) * h1);
        }
    }
}

// =====================================================================
// HEAD via HMMA (R12 champion, frozen): per warp 16 rows, logits in regs,
// quad-shfl softmax.
// =====================================================================
__global__ __launch_bounds__(256, 1)
void head_mma_kernel(const float* __restrict__ b1, const float* __restrict__ b2,
                     const float* __restrict__ gv1, const float* __restrict__ gv2,
                     float* __restrict__ out)
{
    __shared__ u32 Wf1s[2048], Wf2s[2048];
    __shared__ float b1s[NLEV], b2s[NLEV], g1s[NLEV], g2s[NLEV];

    const int t = threadIdx.x;
    for (int i = t; i < 2048; i += 256) { Wf1s[i] = g_Wf1[i]; Wf2s[i] = g_Wf2[i]; }
    b1s[t] = b1[t]; b2s[t] = b2[t]; g1s[t] = gv1[t]; g2s[t] = gv2[t];
    __syncthreads();

    const int warp = t >> 5, lane = t & 31;
    const int qr = lane >> 2, qc = lane & 3;
    const int rbase = blockIdx.x * 128 + warp * 16;

    const __half* h2p = g_h2h + (size_t)rbase * G2U;
    u32 a[4];
    a[0] = *(const u32*)&h2p[qr * G2U + 2 * qc];
    a[1] = *(const u32*)&h2p[(qr + 8) * G2U + 2 * qc];
    a[2] = *(const u32*)&h2p[qr * G2U + 2 * qc + 8];
    a[3] = *(const u32*)&h2p[(qr + 8) * G2U + 2 * qc + 8];

    float v[32][4];
    float mx0 = -1e30f, mx1 = -1e30f;
#pragma unroll
    for (int tt = 0; tt < 32; ++tt) {
        const int fi = (tt * 32 + lane) * 2;
        u32 bw1[2] = { Wf1s[fi], Wf1s[fi + 1] };
        u32 bw2[2] = { Wf2s[fi], Wf2s[fi + 1] };
        const int l = tt * 8 + 2 * qc;
        const float B1x = b1s[l], B1y = b1s[l + 1];
        const float B2x = b2s[l], B2y = b2s[l + 1];
        const float G1x = g1s[l], G1y = g1s[l + 1];
        const float G2x = g2s[l], G2y = g2s[l + 1];
        float d[4] = { B1x, B1y, B1x, B1y };
        float e[4] = { B2x, B2y, B2x, B2y };
        MMA16816(d, a, bw1);
        MMA16816(e, a, bw2);
        v[tt][0] = G1x * tanh_fast(d[0]) + G2x * tanh_fast(e[0]);
        v[tt][1] = G1y * tanh_fast(d[1]) + G2y * tanh_fast(e[1]);
        v[tt][2] = G1x * tanh_fast(d[2]) + G2x * tanh_fast(e[2]);
        v[tt][3] = G1y * tanh_fast(d[3]) + G2y * tanh_fast(e[3]);
        mx0 = fmaxf(mx0, fmaxf(v[tt][0], v[tt][1]));
        mx1 = fmaxf(mx1, fmaxf(v[tt][2], v[tt][3]));
    }
    mx0 = fmaxf(mx0, __shfl_xor_sync(0xffffffffu, mx0, 1));
    mx0 = fmaxf(mx0, __shfl_xor_sync(0xffffffffu, mx0, 2));
    mx1 = fmaxf(mx1, __shfl_xor_sync(0xffffffffu, mx1, 1));
    mx1 = fmaxf(mx1, __shfl_xor_sync(0xffffffffu, mx1, 2));

    float s0 = 0.f, s1 = 0.f;
#pragma unroll
    for (int tt = 0; tt < 32; ++tt) {
        v[tt][0] = __expf(v[tt][0] - mx0);
        v[tt][1] = __expf(v[tt][1] - mx0);
        v[tt][2] = __expf(v[tt][2] - mx1);
        v[tt][3] = __expf(v[tt][3] - mx1);
        s0 += v[tt][0] + v[tt][1];
        s1 += v[tt][2] + v[tt][3];
    }
    s0 += __shfl_xor_sync(0xffffffffu, s0, 1);
    s0 += __shfl_xor_sync(0xffffffffu, s0, 2);
    s1 += __shfl_xor_sync(0xffffffffu, s1, 1);
    s1 += __shfl_xor_sync(0xffffffffu, s1, 2);
    const float i0 = __fdividef(1.f, s0);
    const float i1 = __fdividef(1.f, s1);

    float* o0 = out + (size_t)(rbase + qr) * NLEV;
    float* o1 = out + (size_t)(rbase + qr + 8) * NLEV;
#pragma unroll
    for (int tt = 0; tt < 32; ++tt) {
        const int l = tt * 8 + 2 * qc;
        *(float2*)&o0[l] = make_float2(v[tt][0] * i0, v[tt][1] * i0);
        *(float2*)&o1[l] = make_float2(v[tt][2] * i1, v[tt][3] * i1);
    }
}

// =====================================================================
extern "C" void kernel_launch(void* const* d_in, const int* in_sizes, int n_in,
                              void* d_out, int out_size)
{
    const float* x1   = (const float*)d_in[0];
    const float* x2   = (const float*)d_in[1];
    const float* g1k  = (const float*)d_in[2];
    const float* g1b  = (const float*)d_in[4];
    const float* g2k  = (const float*)d_in[5];
    const float* g2b  = (const float*)d_in[7];
    const float* fw1  = (const float*)d_in[8];
    const float* fb1  = (const float*)d_in[9];
    const float* fw2  = (const float*)d_in[10];
    const float* fb2  = (const float*)d_in[11];
    const float* fg1  = (const float*)d_in[12];
    const float* fg2  = (const float*)d_in[13];
    float* out = (float*)d_out;

    cudaFuncSetAttribute(gemm1_mma_kernel,
                         cudaFuncAttributeMaxDynamicSharedMemorySize, G1_SMEM);
    cudaFuncSetAttribute(gemm2_mma_kernel,
                         cudaFuncAttributeMaxDynamicSharedMemorySize, G2_SMEM);

    prep_kernel<<<NPREP, 256>>>(x1, x2, g1k, g2k, fw1, fw2);
    gemm1_mma_kernel<<<dim3(12, NB / 128), 256, G1_SMEM>>>(g1b);
    gemm2_mma_kernel<<<NB / 128, 256, G2_SMEM>>>(g2b);
    head_mma_kernel<<<NB / 128, 256>>>(fb1, fb2, fg1, fg2, out);
}

// round 16
// speedup vs baseline: 1.2064x; 1.0173x over previous
#include <cuda_runtime.h>
#include <cuda_fp16.h>
#include <cstdint>

// ---------------- problem constants ----------------
#define NB     65536
#define IN1    384
#define IN2    128
#define KDIM   512
#define G1U    384
#define N1     1152
#define G2U    16
#define NLEV   256

typedef unsigned long long u64;
typedef unsigned int u32;

// ---------------- device scratch ----------------
__device__ __half g_Ah[(size_t)NB * KDIM];     // fp16 concat(x1,x2)
__device__ __half g_Bh[(size_t)N1 * KDIM];     // reordered+transposed W1
__device__ __half g_h1h[(size_t)NB * G1U];     // fp16 h1
__device__ __half g_B2[(size_t)48 * G1U];      // transposed W2
__device__ __half g_h2h[(size_t)NB * G2U];     // fp16 h2
__device__ u32    g_Wf1[2048];                 // head W1 in MMA B-fragment order
__device__ u32    g_Wf2[2048];                 // head W2 in MMA B-fragment order

// ---------------- helpers ----------------
__device__ __forceinline__ u32 smem_u32(const void* p) {
    u32 a;
    asm("{ .reg .u64 t; cvta.to.shared.u64 t, %1; cvt.u32.u64 %0, t; }" : "=r"(a) : "l"(p));
    return a;
}
__device__ __forceinline__ u32 swz(u32 x) { return x ^ ((x >> 3) & 0x70); }

#define CP_ASYNC16(dst, src) \
    asm volatile("cp.async.cg.shared.global [%0], [%1], 16;" :: "r"(dst), "l"(src) : "memory")
#define CP_COMMIT() asm volatile("cp.async.commit_group;" ::: "memory")
#define CP_WAIT1()  asm volatile("cp.async.wait_group 1;" ::: "memory")

#define LDSM_X4(r0, r1, r2, r3, addr) \
    asm volatile("ldmatrix.sync.aligned.m8n8.x4.shared.b16 {%0,%1,%2,%3}, [%4];" \
        : "=r"(r0), "=r"(r1), "=r"(r2), "=r"(r3) : "r"(addr))

#define MMA16816(d, a, b) \
    asm volatile("mma.sync.aligned.m16n8k16.row.col.f32.f16.f16.f32 " \
        "{%0,%1,%2,%3},{%4,%5,%6,%7},{%8,%9},{%0,%1,%2,%3};" \
        : "+f"((d)[0]), "+f"((d)[1]), "+f"((d)[2]), "+f"((d)[3]) \
        : "r"((a)[0]), "r"((a)[1]), "r"((a)[2]), "r"((a)[3]), "r"((b)[0]), "r"((b)[1]))

// ---- fast gate math: 1 MUFU per tanh ----
__device__ __forceinline__ float tanh_fast(float x) {
    float y;
    asm("tanh.approx.f32 %0, %1;" : "=f"(y) : "f"(x));
    return y;
}
__device__ __forceinline__ float sigmoid_fast(float x) {
    return fmaf(0.5f, tanh_fast(0.5f * x), 0.5f);
}

// =====================================================================
// Combined prep kernel (single launch)  (R15, frozen)
// =====================================================================
#define NBA   (NB * (KDIM / 8) / 256)     // 16384
#define NTW1  ((N1 / 64) * (KDIM / 64))   // 144
#define NBW2  ((G1U * 48 + 255) / 256)    // 72
#define NPREP (NBA + NTW1 + NBW2 + 1)

__global__ __launch_bounds__(256)
void prep_kernel(const float* __restrict__ x1, const float* __restrict__ x2,
                 const float* __restrict__ W1, const float* __restrict__ W2,
                 const float* __restrict__ hw1, const float* __restrict__ hw2)
{
    const int b = blockIdx.x;
    const int t = threadIdx.x;
    if (b < NBA) {
        size_t i8 = (size_t)b * 256 + t;
        int m  = (int)(i8 >> 6);
        int c8 = ((int)i8 & 63) * 8;
        const float4* s;
        if (c8 < IN1) s = (const float4*)(x1 + (size_t)m * IN1 + c8);
        else          s = (const float4*)(x2 + (size_t)m * IN2 + (c8 - IN1));
        float4 v0 = s[0], v1 = s[1];
        __half2 h0 = __floats2half2_rn(v0.x, v0.y);
        __half2 h1 = __floats2half2_rn(v0.z, v0.w);
        __half2 h2 = __floats2half2_rn(v1.x, v1.y);
        __half2 h3 = __floats2half2_rn(v1.z, v1.w);
        uint4 o;
        o.x = *(u32*)&h0; o.y = *(u32*)&h1; o.z = *(u32*)&h2; o.w = *(u32*)&h3;
        *(uint4*)&g_Ah[(size_t)m * KDIM + c8] = o;
    } else if (b < NBA + NTW1) {
        __shared__ __half sm[64][72];
        const int tile = b - NBA;
        const int c0 = (tile % (N1 / 64)) * 64;
        const int k0 = (tile / (N1 / 64)) * 64;
#pragma unroll
        for (int i = 0; i < 4; ++i) {
            int idx = t + i * 256;
            int kr = idx >> 4, c4 = (idx & 15) * 4;
            float4 v = *(const float4*)(W1 + (size_t)(k0 + kr) * N1 + c0 + c4);
            sm[c4 + 0][kr] = __float2half_rn(v.x);
            sm[c4 + 1][kr] = __float2half_rn(v.y);
            sm[c4 + 2][kr] = __float2half_rn(v.z);
            sm[c4 + 3][kr] = __float2half_rn(v.w);
        }
        __syncthreads();
        {
            int lc = t >> 2, kc = (t & 3) * 16;
            int c = c0 + lc;
            int g = c / G1U, j = c % G1U;
            int n = (j >> 4) * 48 + g * 16 + (j & 15);
            uint4 o0 = *(uint4*)&sm[lc][kc];
            uint4 o1 = *(uint4*)&sm[lc][kc + 8];
            uint4* dst = (uint4*)&g_Bh[(size_t)n * KDIM + k0 + kc];
            dst[0] = o0;
            dst[1] = o1;
        }
    } else if (b < NBA + NTW1 + NBW2) {
        int idx = (b - NBA - NTW1) * 256 + t;
        if (idx < G1U * 48) {
            int k = idx / 48, c = idx % 48;
            g_B2[(size_t)c * G1U + k] = __float2half_rn(W2[idx]);
        }
    } else {
#pragma unroll
        for (int i = t; i < 1024; i += 256) {
            int tt = i >> 5, lane = i & 31;
            int k0 = (lane & 3) * 2;
            int n  = tt * 8 + (lane >> 2);
            __half2 p10 = __floats2half2_rn(hw1[k0 * NLEV + n],       hw1[(k0 + 1) * NLEV + n]);
            __half2 p11 = __floats2half2_rn(hw1[(k0 + 8) * NLEV + n], hw1[(k0 + 9) * NLEV + n]);
            __half2 p20 = __floats2half2_rn(hw2[k0 * NLEV + n],       hw2[(k0 + 1) * NLEV + n]);
            __half2 p21 = __floats2half2_rn(hw2[(k0 + 8) * NLEV + n], hw2[(k0 + 9) * NLEV + n]);
            g_Wf1[2 * i]     = *(u32*)&p10;
            g_Wf1[2 * i + 1] = *(u32*)&p11;
            g_Wf2[2 * i]     = *(u32*)&p20;
            g_Wf2[2 * i + 1] = *(u32*)&p21;
        }
    }
}

// =====================================================================
// GEMM1: h1 = GRU1(A, h=0).  fp16 single-pass HMMA.  (R12 champion, frozen)
// =====================================================================
#define G1_STAGE  28672            // 16KB A + 12KB B
#define G1_OFFB   16384
#define G1_NSTG   3
#define G1_BIAS   (G1_NSTG * G1_STAGE) // 86016
#define G1_SMEM   (G1_BIAS + 512)

__device__ __forceinline__ void load_stage_g1(u32 sb, int s, int kt, int m0, int nb, int tid)
{
    const int k0 = kt * 64;
    const u32 base = sb + s * G1_STAGE;
    const char* Ap = (const char*)g_Ah;
    const char* Bp = (const char*)g_Bh;
#pragma unroll
    for (int i = 0; i < 4; ++i) {
        int c = tid + i * 256;
        int row = c >> 3, cb = c & 7;
        u32 dst = base + swz(row * 128 + cb * 16);
        const char* src = Ap + (size_t)(m0 + row) * (KDIM * 2) + k0 * 2 + cb * 16;
        CP_ASYNC16(dst, src);
    }
#pragma unroll
    for (int i = 0; i < 3; ++i) {
        int c = tid + i * 256;
        int row = c >> 3, cb = c & 7;
        u32 dst = base + G1_OFFB + swz(row * 128 + cb * 16);
        const char* src = Bp + (size_t)(nb * 96 + row) * (KDIM * 2) + k0 * 2 + cb * 16;
        CP_ASYNC16(dst, src);
    }
}

__global__ __launch_bounds__(256, 2)
void gemm1_mma_kernel(const float* __restrict__ bias)
{
    extern __shared__ char smem[];
    const u32 sb = smem_u32(smem);
    const int tid  = threadIdx.x;
    const int warp = tid >> 5, lane = tid & 31;
    const int wm = warp & 3;
    const int wn = warp >> 2;
    const int nb = blockIdx.x;
    const int m0 = blockIdx.y * 128;

    float* czs  = (float*)(smem + G1_BIAS);
    float* crs  = czs + 32;
    float* ch0s = czs + 64;
    float* ch1s = czs + 96;
    if (tid < 32) {
        int j = nb * 32 + tid;
        czs[tid]  = bias[j]         + bias[N1 + j];
        crs[tid]  = bias[G1U + j]   + bias[N1 + G1U + j];
        ch0s[tid] = bias[2 * G1U + j];
        ch1s[tid] = bias[N1 + 2 * G1U + j];
    }

    float acc[2][6][4];
#pragma unroll
    for (int mi = 0; mi < 2; ++mi)
#pragma unroll
        for (int ni = 0; ni < 6; ++ni)
#pragma unroll
            for (int e = 0; e < 4; ++e) acc[mi][ni][e] = 0.f;

    const int a_row = 32 * wm + (lane & 15);
    const int a_kb  = (lane & 16) ? 16 : 0;
    const int b_row = 48 * wn + (lane & 7) + ((lane & 16) ? 8 : 0);
    const int b_kb  = (lane & 8) ? 16 : 0;

    load_stage_g1(sb, 0, 0, m0, nb, tid); CP_COMMIT();
    load_stage_g1(sb, 1, 1, m0, nb, tid); CP_COMMIT();

    for (int kt = 0; kt < 8; ++kt) {
        const int s = kt % G1_NSTG;
        CP_WAIT1();
        __syncthreads();
        if (kt + 2 < 8) load_stage_g1(sb, (kt + 2) % G1_NSTG, kt + 2, m0, nb, tid);
        CP_COMMIT();

        const u32 abase = sb + s * G1_STAGE;
        const u32 bbase = abase + G1_OFFB;
#pragma unroll
        for (int ks = 0; ks < 4; ++ks) {
            u32 af[2][4], bf[3][4];
#pragma unroll
            for (int mi = 0; mi < 2; ++mi) {
                u32 ad = abase + swz((u32)(a_row + mi * 16) * 128 + ks * 32 + a_kb);
                LDSM_X4(af[mi][0], af[mi][1], af[mi][2], af[mi][3], ad);
            }
#pragma unroll
            for (int bi = 0; bi < 3; ++bi) {
                u32 bd = bbase + swz((u32)(b_row + bi * 16) * 128 + ks * 32 + b_kb);
                LDSM_X4(bf[bi][0], bf[bi][1], bf[bi][2], bf[bi][3], bd);
            }
#pragma unroll
            for (int mi = 0; mi < 2; ++mi)
#pragma unroll
                for (int bi = 0; bi < 3; ++bi) {
                    MMA16816(acc[mi][2 * bi],     af[mi], (&bf[bi][0]));
                    MMA16816(acc[mi][2 * bi + 1], af[mi], (&bf[bi][2]));
                }
        }
    }

    const int qr = lane >> 2, qc = lane & 3;
#pragma unroll
    for (int mi = 0; mi < 2; ++mi) {
#pragma unroll
        for (int nip = 0; nip < 2; ++nip) {
            const int ul = wn * 16 + 8 * nip + 2 * qc;
            const int j0 = nb * 32 + ul;
            const float cz0 = czs[ul],  cz1 = czs[ul + 1];
            const float cr0 = crs[ul],  cr1 = crs[ul + 1];
            const float c00 = ch0s[ul], c01 = ch0s[ul + 1];
            const float c10 = ch1s[ul], c11 = ch1s[ul + 1];
            const float* az = acc[mi][nip];
            const float* ar = acc[mi][nip + 2];
            const float* ah = acc[mi][nip + 4];
#pragma unroll
            for (int half = 0; half < 2; ++half) {
                const int row = m0 + 32 * wm + 16 * mi + qr + half * 8;
                float z0 = sigmoid_fast(az[2 * half]     + cz0);
                float z1 = sigmoid_fast(az[2 * half + 1] + cz1);
                float r0 = sigmoid_fast(ar[2 * half]     + cr0);
                float r1 = sigmoid_fast(ar[2 * half + 1] + cr1);
                float h0 = tanh_fast(ah[2 * half]     + c00 + r0 * c10);
                float h1 = tanh_fast(ah[2 * half + 1] + c01 + r1 * c11);
                *(__half2*)&g_h1h[(size_t)row * G1U + j0] =
                    __floats2half2_rn((1.f - z0) * h0, (1.f - z1) * h1);
            }
        }
    }
}

// =====================================================================
// GEMM2: h2 = GRU2(h1, h=0) -> fp16 g_h2h.  (R12, frozen)
// =====================================================================
#define G2_STAGE  22528
#define G2_OFFB   16384
#define G2_BIAS   (3 * G2_STAGE) // 67584
#define G2_SMEM   (G2_BIAS + 512)

__device__ __forceinline__ void load_stage_g2(u32 sb, int s, int kt, int m0, int tid)
{
    const int k0 = kt * 64;
    const u32 base = sb + s * G2_STAGE;
    const char* Ap = (const char*)g_h1h;
    const char* Bp = (const char*)g_B2;
#pragma unroll
    for (int i = 0; i < 4; ++i) {
        int c = tid + i * 256;
        int row = c >> 3, cb = c & 7;
        u32 dst = base + swz(row * 128 + cb * 16);
        const char* src = Ap + (size_t)(m0 + row) * (G1U * 2) + k0 * 2 + cb * 16;
        CP_ASYNC16(dst, src);
    }
#pragma unroll
    for (int i = 0; i < 2; ++i) {
        int c = tid + i * 256;
        if (c < 384) {
            int row = c >> 3, cb = c & 7;
            u32 dst = base + G2_OFFB + swz(row * 128 + cb * 16);
            const char* src = Bp + (size_t)row * (G1U * 2) + k0 * 2 + cb * 16;
            CP_ASYNC16(dst, src);
        }
    }
}

__global__ __launch_bounds__(256, 2)
void gemm2_mma_kernel(const float* __restrict__ bias)
{
    extern __shared__ char smem[];
    const u32 sb = smem_u32(smem);
    const int tid  = threadIdx.x;
    const int warp = tid >> 5, lane = tid & 31;
    const int m0 = blockIdx.x * 128;

    float* czs  = (float*)(smem + G2_BIAS);
    float* crs  = czs + 16;
    float* ch0s = czs + 32;
    float* ch1s = czs + 48;
    if (tid < 16) {
        czs[tid]  = bias[tid]      + bias[48 + tid];
        crs[tid]  = bias[16 + tid] + bias[64 + tid];
        ch0s[tid] = bias[32 + tid];
        ch1s[tid] = bias[80 + tid];
    }

    float acc[6][4];
#pragma unroll
    for (int ni = 0; ni < 6; ++ni)
#pragma unroll
        for (int e = 0; e < 4; ++e) acc[ni][e] = 0.f;

    const int a_row = 16 * warp + (lane & 15);
    const int a_kb  = (lane & 16) ? 16 : 0;
    const int b_row = (lane & 7) + ((lane & 16) ? 8 : 0);
    const int b_kb  = (lane & 8) ? 16 : 0;

    load_stage_g2(sb, 0, 0, m0, tid); CP_COMMIT();
    load_stage_g2(sb, 1, 1, m0, tid); CP_COMMIT();

    for (int kt = 0; kt < 6; ++kt) {
        const int s = kt % 3;
        CP_WAIT1();
        __syncthreads();
        if (kt + 2 < 6) load_stage_g2(sb, (kt + 2) % 3, kt + 2, m0, tid);
        CP_COMMIT();

        const u32 abase = sb + s * G2_STAGE;
        const u32 bbase = abase + G2_OFFB;
#pragma unroll
        for (int ks = 0; ks < 4; ++ks) {
            u32 af[4], bf[3][4];
            u32 ad = abase + swz((u32)a_row * 128 + ks * 32 + a_kb);
            LDSM_X4(af[0], af[1], af[2], af[3], ad);
#pragma unroll
            for (int bi = 0; bi < 3; ++bi) {
                u32 bd = bbase + swz((u32)(b_row + bi * 16) * 128 + ks * 32 + b_kb);
                LDSM_X4(bf[bi][0], bf[bi][1], bf[bi][2], bf[bi][3], bd);
            }
#pragma unroll
            for (int bi = 0; bi < 3; ++bi) {
                MMA16816(acc[2 * bi],     af, (&bf[bi][0]));
                MMA16816(acc[2 * bi + 1], af, (&bf[bi][2]));
            }
        }
    }

    const int qr = lane >> 2, qc = lane & 3;
#pragma unroll
    for (int nip = 0; nip < 2; ++nip) {
        const int u0 = 8 * nip + 2 * qc;
        const float cz0 = czs[u0],  cz1 = czs[u0 + 1];
        const float cr0 = crs[u0],  cr1 = crs[u0 + 1];
        const float c00 = ch0s[u0], c01 = ch0s[u0 + 1];
        const float c10 = ch1s[u0], c11 = ch1s[u0 + 1];
        const float* az = acc[nip];
        const float* ar = acc[nip + 2];
        const float* ah = acc[nip + 4];
#pragma unroll
        for (int half = 0; half < 2; ++half) {
            const int row = m0 + 16 * warp + qr + half * 8;
            float z0 = sigmoid_fast(az[2 * half]     + cz0);
            float z1 = sigmoid_fast(az[2 * half + 1] + cz1);
            float r0 = sigmoid_fast(ar[2 * half]     + cr0);
            float r1 = sigmoid_fast(ar[2 * half + 1] + cr1);
            float h0 = tanh_fast(ah[2 * half]     + c00 + r0 * c10);
            float h1 = tanh_fast(ah[2 * half + 1] + c01 + r1 * c11);
            *(__half2*)&g_h2h[(size_t)row * G2U + u0] =
                __floats2half2_rn((1.f - z0) * h0, (1.f - z1) * h1);
        }
    }
}

// =====================================================================
// HEAD v3: single-pass softmax (logits bounded by |g1|+|g2| -> no max
// shift needed), exp stored packed fp16 -> ~120 regs -> 2 CTAs/SM.
// Fused (b1,b2,g1,g2) float4 smem -> 2 LDS.128 per tile.
// =====================================================================
__global__ __launch_bounds__(256, 2)
void head_mma_kernel(const float* __restrict__ b1, const float* __restrict__ b2,
                     const float* __restrict__ gv1, const float* __restrict__ gv2,
                     float* __restrict__ out)
{
    __shared__ u32 Wf1s[2048], Wf2s[2048];
    __shared__ float4 cbs[NLEV];   // (b1, b2, g1, g2)

    const int t = threadIdx.x;
    for (int i = t; i < 2048; i += 256) { Wf1s[i] = g_Wf1[i]; Wf2s[i] = g_Wf2[i]; }
    cbs[t] = make_float4(b1[t], b2[t], gv1[t], gv2[t]);
    __syncthreads();

    const int warp = t >> 5, lane = t & 31;
    const int qr = lane >> 2, qc = lane & 3;
    const int rbase = blockIdx.x * 128 + warp * 16;

    const __half* h2p = g_h2h + (size_t)rbase * G2U;
    u32 a[4];
    a[0] = *(const u32*)&h2p[qr * G2U + 2 * qc];
    a[1] = *(const u32*)&h2p[(qr + 8) * G2U + 2 * qc];
    a[2] = *(const u32*)&h2p[qr * G2U + 2 * qc + 8];
    a[3] = *(const u32*)&h2p[(qr + 8) * G2U + 2 * qc + 8];

    u32 ve[32][2];                 // packed fp16 exp values
    float s0 = 0.f, s1 = 0.f;
#pragma unroll
    for (int tt = 0; tt < 32; ++tt) {
        const int fi = (tt * 32 + lane) * 2;
        u32 bw1[2] = { Wf1s[fi], Wf1s[fi + 1] };
        u32 bw2[2] = { Wf2s[fi], Wf2s[fi + 1] };
        const int l = tt * 8 + 2 * qc;
        const float4 c0 = cbs[l];
        const float4 c1 = cbs[l + 1];
        float d[4] = { c0.x, c1.x, c0.x, c1.x };
        float e[4] = { c0.y, c1.y, c0.y, c1.y };
        MMA16816(d, a, bw1);
        MMA16816(e, a, bw2);
        // logits bounded: |v| <= |g1|+|g2|  ->  exp safe without max shift
        float e0 = __expf(c0.z * tanh_fast(d[0]) + c0.w * tanh_fast(e[0]));
        float e1 = __expf(c1.z * tanh_fast(d[1]) + c1.w * tanh_fast(e[1]));
        float e2 = __expf(c0.z * tanh_fast(d[2]) + c0.w * tanh_fast(e[2]));
        float e3 = __expf(c1.z * tanh_fast(d[3]) + c1.w * tanh_fast(e[3]));
        __half2 p0 = __floats2half2_rn(e0, e1);
        __half2 p1 = __floats2half2_rn(e2, e3);
        ve[tt][0] = *(u32*)&p0;
        ve[tt][1] = *(u32*)&p1;
        s0 += e0 + e1;
        s1 += e2 + e3;
    }
    s0 += __shfl_xor_sync(0xffffffffu, s0, 1);
    s0 += __shfl_xor_sync(0xffffffffu, s0, 2);
    s1 += __shfl_xor_sync(0xffffffffu, s1, 1);
    s1 += __shfl_xor_sync(0xffffffffu, s1, 2);
    const float i0 = __fdividef(1.f, s0);
    const float i1 = __fdividef(1.f, s1);

    float* o0 = out + (size_t)(rbase + qr) * NLEV;
    float* o1 = out + (size_t)(rbase + qr + 8) * NLEV;
#pragma unroll
    for (int tt = 0; tt < 32; ++tt) {
        const int l = tt * 8 + 2 * qc;
        float2 u0 = __half22float2(*(__half2*)&ve[tt][0]);
        float2 u1 = __half22float2(*(__half2*)&ve[tt][1]);
        *(float2*)&o0[l] = make_float2(u0.x * i0, u0.y * i0);
        *(float2*)&o1[l] = make_float2(u1.x * i1, u1.y * i1);
    }
}

// =====================================================================
extern "C" void kernel_launch(void* const* d_in, const int* in_sizes, int n_in,
                              void* d_out, int out_size)
{
    const float* x1   = (const float*)d_in[0];
    const float* x2   = (const float*)d_in[1];
    const float* g1k  = (const float*)d_in[2];
    const float* g1b  = (const float*)d_in[4];
    const float* g2k  = (const float*)d_in[5];
    const float* g2b  = (const float*)d_in[7];
    const float* fw1  = (const float*)d_in[8];
    const float* fb1  = (const float*)d_in[9];
    const float* fw2  = (const float*)d_in[10];
    const float* fb2  = (const float*)d_in[11];
    const float* fg1  = (const float*)d_in[12];
    const float* fg2  = (const float*)d_in[13];
    float* out = (float*)d_out;

    cudaFuncSetAttribute(gemm1_mma_kernel,
                         cudaFuncAttributeMaxDynamicSharedMemorySize, G1_SMEM);
    cudaFuncSetAttribute(gemm2_mma_kernel,
                         cudaFuncAttributeMaxDynamicSharedMemorySize, G2_SMEM);

    prep_kernel<<<NPREP, 256>>>(x1, x2, g1k, g2k, fw1, fw2);
    gemm1_mma_kernel<<<dim3(12, NB / 128), 256, G1_SMEM>>>(g1b);
    gemm2_mma_kernel<<<NB / 128, 256, G2_SMEM>>>(g2b);
    head_mma_kernel<<<NB / 128, 256>>>(fb1, fb2, fg1, fg2, out);
}